// round 13
// baseline (speedup 1.0000x reference)
#include <cuda_runtime.h>
#include <cstdint>

// ============================ problem constants ============================
static constexpr int E_  = 8;
static constexpr int M_  = 1024;
static constexpr int H_  = 2048;   // K of GEMM1, N of GEMM2
static constexpr int I2_ = 4096;   // w1 out cols (gate/up interleaved)
static constexpr int IN_ = 2048;   // intermediate = I2/2 = K of GEMM2
static constexpr int KDIM = 2048;  // K of both GEMMs

static constexpr int TM = 128, TN = 128, KC = 32;
static constexpr int NSTG = 3;
static constexpr int NIT = KDIM / KC;          // 64
static constexpr int THREADS = 128;            // 4 warps, 2x2 grid of 64x64 warp tiles

// Both tiles [128 rows][32 k-floats], row stride 36 floats.
// ldmatrix conflict-freedom: 16B-chunk index = (9*row + chunk) mod 8,
// distinct for any 8 consecutive rows at fixed chunk.
static constexpr int TSTR = 36;
static constexpr int T_FLOATS = 128 * TSTR;              // 4608
static constexpr int STGF = 2 * T_FLOATS;                // 9216 floats (A + B)
static constexpr int SMEM_TOTAL = NSTG * STGF * 4;       // 110592 B (2 CTAs/SM = 221KB)

// ============================ device scratch ============================
__device__ float g_xr [E_ * M_  * KDIM];   // tf32-rounded X       [e][m][k]
__device__ float g_w1t[E_ * I2_ * KDIM];   // tf32 w1 transposed   [e][n][k]
__device__ float g_w2t[E_ * H_  * IN_ ];   // tf32 w2 transposed   [e][n][k]
__device__ float g_act[E_ * M_  * IN_ ];   // tf32 activation      [e][m][i]

// ============================ helpers ============================
__device__ __forceinline__ uint32_t smem_u32(const void* p) {
    uint32_t a;
    asm("{ .reg .u64 t; cvta.to.shared.u64 t, %1; cvt.u32.u64 %0, t; }" : "=r"(a) : "l"(p));
    return a;
}

// fp32 -> tf32 round-to-nearest (HW), bits in b32
__device__ __forceinline__ float rtf32(float x) {
    uint32_t y;
    asm("cvt.rna.tf32.f32 %0, %1;" : "=r"(y) : "r"(__float_as_uint(x)));
    return __uint_as_float(y);
}

__device__ __forceinline__ void cpa16(uint32_t s, const float* g) {
    asm volatile("cp.async.cg.shared.global [%0], [%1], 16;" :: "r"(s), "l"(g));
}
#define CP_COMMIT() asm volatile("cp.async.commit_group;" ::: "memory")
#define CP_WAIT1()  asm volatile("cp.async.wait_group 1;" ::: "memory")

__device__ __forceinline__ void ldsm_x4(uint32_t& r0, uint32_t& r1,
                                        uint32_t& r2, uint32_t& r3, uint32_t addr) {
    asm volatile("ldmatrix.sync.aligned.m8n8.x4.shared.b16 {%0,%1,%2,%3}, [%4];"
                 : "=r"(r0), "=r"(r1), "=r"(r2), "=r"(r3) : "r"(addr));
}

// m16n8k8 tf32 MMA, D += A*B
__device__ __forceinline__ void mma8(float* d, const uint32_t* a, const uint32_t* b) {
    asm volatile(
        "mma.sync.aligned.m16n8k8.row.col.f32.tf32.tf32.f32 "
        "{%0,%1,%2,%3},{%4,%5,%6,%7},{%8,%9},{%0,%1,%2,%3};"
        : "+f"(d[0]), "+f"(d[1]), "+f"(d[2]), "+f"(d[3])
        : "r"(a[0]), "r"(a[1]), "r"(a[2]), "r"(a[3]), "r"(b[0]), "r"(b[1]));
}

__device__ __forceinline__ float swiglu(float gate, float up) {
    gate = fminf(gate, 7.0f);
    up   = fminf(fmaxf(up, -7.0f), 7.0f);
    float glu = gate * (1.0f / (1.0f + __expf(-1.702f * gate)));
    return (up + 1.0f) * glu;
}

// ============================ prep kernels ============================
__global__ __launch_bounds__(256) void round_x(const float* __restrict__ src) {
    size_t n4 = (size_t)E_ * M_ * KDIM / 4;
    const float4* s4 = (const float4*)src;
    float4* d4 = (float4*)g_xr;
    for (size_t i = (size_t)blockIdx.x * blockDim.x + threadIdx.x; i < n4;
         i += (size_t)gridDim.x * blockDim.x) {
        float4 v = s4[i];
        v.x = rtf32(v.x); v.y = rtf32(v.y); v.z = rtf32(v.z); v.w = rtf32(v.w);
        d4[i] = v;
    }
}

// dst[e][c][r] = rtf32(src[e][r][c]);  sel 0 -> g_w1t, sel 1 -> g_w2t
__global__ __launch_bounds__(256) void transpose_rt(const float* __restrict__ src,
                                                    int sel, int R, int C) {
    __shared__ float t[32][33];
    int e = blockIdx.z;
    const float* s = src + (size_t)e * R * C;
    float* d = (sel == 0 ? g_w1t : g_w2t) + (size_t)e * R * C;
    int c0 = blockIdx.x * 32, r0 = blockIdx.y * 32;
    int tx = threadIdx.x, ty = threadIdx.y;
#pragma unroll
    for (int i = 0; i < 32; i += 8)
        t[ty + i][tx] = s[(size_t)(r0 + ty + i) * C + c0 + tx];
    __syncthreads();
#pragma unroll
    for (int i = 0; i < 32; i += 8)
        d[(size_t)(c0 + ty + i) * R + r0 + tx] = rtf32(t[tx][ty + i]);
}

// ============================ GEMM ============================
// MODE 0: act = swiglu(X @ w1 + b1) -> g_act   (N total = 4096; B = g_w1t [n][k])
// MODE 1: out = act @ w2 + b2                   (N total = 2048; B = g_w2t [n][k])
template <int MODE>
__global__ __launch_bounds__(THREADS, 2) void gemm_mma(const float* __restrict__ Ag,
                                                       const float* __restrict__ Bg,
                                                       const float* __restrict__ bias,
                                                       float* __restrict__ outp) {
    constexpr int NTOT = (MODE == 0) ? I2_ : H_;
    extern __shared__ __align__(16) float sm[];
    const uint32_t sb = smem_u32(sm);

    const int tid = threadIdx.x;
    const int wid = tid >> 5, lane = tid & 31;
    const int wm = wid >> 1, wn = wid & 1;     // 2 x 2 warp grid, 64x64 tiles
    const int g = lane >> 2, l4 = lane & 3;
    const int e = blockIdx.z;
    const int m0 = blockIdx.y * TM, n0 = blockIdx.x * TN;

    const float* Ae = Ag + (size_t)e * M_ * KDIM;
    const float* Be = Bg + (size_t)e * NTOT * KDIM;   // [n][k]

    float acc[4][8][4] = {};

    // cp.async chunk coordinates (identical pattern for A and B tiles)
    const int cr = tid >> 3, cc = (tid & 7) * 4;     // rows 0..15(+16p), 8 chunks/row

    // ldmatrix A: row = wm*64 + mt*16 + (lane&15), chunk = 2*ks + (lane>>4)
    const int a_row = wm * 64 + (lane & 15);
    const int a_chk = lane >> 4;
    // ldmatrix B: row = wn*64 + p*16 + ((lane>>4)*8) + (lane&7), chunk = 2*ks + ((lane>>3)&1)
    const int b_row = wn * 64 + ((lane >> 4) * 8) + (lane & 7);
    const int b_chk = (lane >> 3) & 1;

    auto load_stage = [&](int s, int k0) {
        uint32_t abase = sb + (uint32_t)(s * STGF) * 4u;
        uint32_t bbase = abase + (uint32_t)T_FLOATS * 4u;
#pragma unroll
        for (int p = 0; p < 8; p++) {
            int r = cr + p * 16;
            cpa16(abase + (uint32_t)(r * TSTR + cc) * 4u,
                  Ae + (size_t)(m0 + r) * KDIM + k0 + cc);
        }
#pragma unroll
        for (int p = 0; p < 8; p++) {
            int r = cr + p * 16;
            cpa16(bbase + (uint32_t)(r * TSTR + cc) * 4u,
                  Be + (size_t)(n0 + r) * KDIM + k0 + cc);
        }
    };

    // prologue: stages 0 and 1
    load_stage(0, 0);      CP_COMMIT();
    load_stage(1, KC);     CP_COMMIT();

    for (int i = 0; i < NIT; i++) {
        CP_WAIT1();              // stage i resident
        __syncthreads();
        if (i + 2 < NIT) { load_stage((i + 2) % NSTG, (i + 2) * KC); }
        CP_COMMIT();

        const uint32_t As_addr = sb + (uint32_t)((i % NSTG) * STGF) * 4u;
        const uint32_t Bs_addr = As_addr + (uint32_t)T_FLOATS * 4u;

#pragma unroll
        for (int ks = 0; ks < 4; ks++) {
            uint32_t af[4][4], bf[8][2];
#pragma unroll
            for (int mt = 0; mt < 4; mt++) {
                uint32_t addr = As_addr +
                    (uint32_t)((a_row + mt * 16) * TSTR + (2 * ks + a_chk) * 4) * 4u;
                ldsm_x4(af[mt][0], af[mt][1], af[mt][2], af[mt][3], addr);
            }
#pragma unroll
            for (int p = 0; p < 4; p++) {   // nt pairs (2p, 2p+1)
                uint32_t addr = Bs_addr +
                    (uint32_t)((b_row + p * 16) * TSTR + (2 * ks + b_chk) * 4) * 4u;
                ldsm_x4(bf[2 * p][0], bf[2 * p][1], bf[2 * p + 1][0], bf[2 * p + 1][1], addr);
            }
#pragma unroll
            for (int mt = 0; mt < 4; mt++)
#pragma unroll
                for (int nt = 0; nt < 8; nt++)
                    mma8(acc[mt][nt], af[mt], bf[nt]);
        }
    }

    // ============================ epilogue ============================
#pragma unroll
    for (int mt = 0; mt < 4; mt++) {
#pragma unroll
        for (int nt = 0; nt < 8; nt++) {
            int mrow = m0 + wm * 64 + mt * 16 + g;
            int ncol = n0 + wn * 64 + nt * 8 + 2 * l4;
            float2 bv = *(const float2*)&bias[(size_t)e * NTOT + ncol];
            if (MODE == 0) {
                // (even, odd) col pair = (gate, up); store tf32-rounded act
                float a0 = swiglu(acc[mt][nt][0] + bv.x, acc[mt][nt][1] + bv.y);
                float a1 = swiglu(acc[mt][nt][2] + bv.x, acc[mt][nt][3] + bv.y);
                int io = ncol >> 1;
                g_act[((size_t)e * M_ + mrow)     * IN_ + io] = rtf32(a0);
                g_act[((size_t)e * M_ + mrow + 8) * IN_ + io] = rtf32(a1);
            } else {
                float2 v0 = make_float2(acc[mt][nt][0] + bv.x, acc[mt][nt][1] + bv.y);
                float2 v1 = make_float2(acc[mt][nt][2] + bv.x, acc[mt][nt][3] + bv.y);
                *(float2*)&outp[((size_t)e * M_ + mrow)     * H_ + ncol] = v0;
                *(float2*)&outp[((size_t)e * M_ + mrow + 8) * H_ + ncol] = v1;
            }
        }
    }
}

// ============================ launch ============================
extern "C" void kernel_launch(void* const* d_in, const int* in_sizes, int n_in,
                              void* d_out, int out_size) {
    const float* x  = (const float*)d_in[0];
    const float* w1 = (const float*)d_in[1];
    const float* b1 = (const float*)d_in[2];
    const float* w2 = (const float*)d_in[3];
    const float* b2 = (const float*)d_in[4];
    float* out = (float*)d_out;

    cudaFuncSetAttribute(gemm_mma<0>, cudaFuncAttributeMaxDynamicSharedMemorySize, SMEM_TOTAL);
    cudaFuncSetAttribute(gemm_mma<1>, cudaFuncAttributeMaxDynamicSharedMemorySize, SMEM_TOTAL);

    float *actp, *w1tp, *w2tp, *xrp;
    cudaGetSymbolAddress((void**)&actp, g_act);
    cudaGetSymbolAddress((void**)&w1tp, g_w1t);
    cudaGetSymbolAddress((void**)&w2tp, g_w2t);
    cudaGetSymbolAddress((void**)&xrp,  g_xr);

    // prep: round x; transpose+round w1 -> [n][k], w2 -> [n][k]
    round_x<<<1024, 256>>>(x);
    transpose_rt<<<dim3(I2_ / 32, H_ / 32, E_), dim3(32, 8)>>>(w1, 0, H_, I2_);
    transpose_rt<<<dim3(H_ / 32, IN_ / 32, E_), dim3(32, 8)>>>(w2, 1, IN_, H_);

    // GEMM1 + bias + SwiGLU -> g_act
    gemm_mma<0><<<dim3(I2_ / TN, M_ / TM, E_), THREADS, SMEM_TOTAL>>>(xrp, w1tp, b1, nullptr);
    // GEMM2 + bias -> out
    gemm_mma<1><<<dim3(H_ / TN, M_ / TM, E_), THREADS, SMEM_TOTAL>>>(actp, w2tp, b2, out);
}

// round 14
// speedup vs baseline: 1.4329x; 1.4329x over previous
#include <cuda_runtime.h>
#include <cstdint>

// ============================ problem constants ============================
static constexpr int E_  = 8;
static constexpr int M_  = 1024;
static constexpr int H_  = 2048;   // K of GEMM1, N of GEMM2
static constexpr int I2_ = 4096;   // w1 out cols (gate/up interleaved)
static constexpr int IN_ = 2048;   // intermediate = I2/2 = K of GEMM2
static constexpr int KDIM = 2048;  // K of both GEMMs

static constexpr int TM = 128, TN = 128, KC = 32;
static constexpr int NSTG = 3;
static constexpr int NIT = KDIM / KC;          // 64

// A tile [128 m][32 k], row stride 36 floats (ldmatrix conflict-free:
//   16B-chunk index = (9*row + chunk) mod 8 distinct over any 8 consecutive rows).
// B tile [32 k][128 n], row stride 136 floats (scalar LDS conflict-free:
//   bank = (8k + n) mod 32 unique over (l4, g)).
static constexpr int ASTR = 36;
static constexpr int BSTR = 136;
static constexpr int A_FLOATS = TM * ASTR;               // 4608
static constexpr int B_FLOATS = KC * BSTR;               // 4352
static constexpr int STGF = A_FLOATS + B_FLOATS;         // 8960 floats
static constexpr int SMEM_TOTAL = NSTG * STGF * 4;       // 107520 B (2 CTAs/SM)

// ============================ device scratch ============================
__device__ float g_xr [E_ * M_ * KDIM];   // tf32-rounded X    [e][m][k]
__device__ float g_act[E_ * M_ * IN_ ];   // tf32 activation   [e][m][i]

// ============================ helpers ============================
__device__ __forceinline__ uint32_t smem_u32(const void* p) {
    uint32_t a;
    asm("{ .reg .u64 t; cvta.to.shared.u64 t, %1; cvt.u32.u64 %0, t; }" : "=r"(a) : "l"(p));
    return a;
}

// fp32 -> tf32 round-to-nearest (HW), float view
__device__ __forceinline__ float rtf32(float x) {
    uint32_t y;
    asm("cvt.rna.tf32.f32 %0, %1;" : "=r"(y) : "r"(__float_as_uint(x)));
    return __uint_as_float(y);
}
// bits version for fragments
__device__ __forceinline__ uint32_t cvt_tf32(uint32_t x) {
    uint32_t y;
    asm("cvt.rna.tf32.f32 %0, %1;" : "=r"(y) : "r"(x));
    return y;
}

__device__ __forceinline__ void cpa16(uint32_t s, const float* g) {
    asm volatile("cp.async.cg.shared.global [%0], [%1], 16;" :: "r"(s), "l"(g));
}
#define CP_COMMIT() asm volatile("cp.async.commit_group;" ::: "memory")
#define CP_WAIT1()  asm volatile("cp.async.wait_group 1;" ::: "memory")

__device__ __forceinline__ void ldsm_x4(uint32_t& r0, uint32_t& r1,
                                        uint32_t& r2, uint32_t& r3, uint32_t addr) {
    asm volatile("ldmatrix.sync.aligned.m8n8.x4.shared.b16 {%0,%1,%2,%3}, [%4];"
                 : "=r"(r0), "=r"(r1), "=r"(r2), "=r"(r3) : "r"(addr));
}

// m16n8k8 tf32 MMA, D += A*B
__device__ __forceinline__ void mma8(float* d, const uint32_t* a, const uint32_t* b) {
    asm volatile(
        "mma.sync.aligned.m16n8k8.row.col.f32.tf32.tf32.f32 "
        "{%0,%1,%2,%3},{%4,%5,%6,%7},{%8,%9},{%0,%1,%2,%3};"
        : "+f"(d[0]), "+f"(d[1]), "+f"(d[2]), "+f"(d[3])
        : "r"(a[0]), "r"(a[1]), "r"(a[2]), "r"(a[3]), "r"(b[0]), "r"(b[1]));
}

__device__ __forceinline__ float swiglu(float gate, float up) {
    gate = fminf(gate, 7.0f);
    up   = fminf(fmaxf(up, -7.0f), 7.0f);
    float glu = gate * (1.0f / (1.0f + __expf(-1.702f * gate)));
    return (up + 1.0f) * glu;
}

// ============================ prep kernel ============================
__global__ __launch_bounds__(256) void round_x(const float* __restrict__ src) {
    size_t n4 = (size_t)E_ * M_ * KDIM / 4;
    const float4* s4 = (const float4*)src;
    float4* d4 = (float4*)g_xr;
    for (size_t i = (size_t)blockIdx.x * blockDim.x + threadIdx.x; i < n4;
         i += (size_t)gridDim.x * blockDim.x) {
        float4 v = s4[i];
        v.x = rtf32(v.x); v.y = rtf32(v.y); v.z = rtf32(v.z); v.w = rtf32(v.w);
        d4[i] = v;
    }
}

// ============================ GEMM ============================
// MODE 0: act = swiglu(X @ w1 + b1) -> g_act   (B = w1 [k][n], N total = 4096)
// MODE 1: out = act @ w2 + b2                   (B = w2 [k][n], N total = 2048)
// A is pre-rounded tf32; B is raw fp32, rounded in-register on fragments.
template <int MODE>
__global__ __launch_bounds__(256, 2) void gemm_mma(const float* __restrict__ Ag,
                                                   const float* __restrict__ Bg,
                                                   const float* __restrict__ bias,
                                                   float* __restrict__ outp) {
    constexpr int NTOT = (MODE == 0) ? I2_ : H_;
    extern __shared__ __align__(16) float sm[];
    const uint32_t sb = smem_u32(sm);

    const int tid = threadIdx.x;
    const int wid = tid >> 5, lane = tid & 31;
    const int wm = wid >> 2, wn = wid & 3;     // 2 x 4 warp grid, 64x32 tiles
    const int g = lane >> 2, l4 = lane & 3;
    const int e = blockIdx.z;
    const int m0 = blockIdx.y * TM, n0 = blockIdx.x * TN;

    const float* Ae = Ag + (size_t)e * M_ * KDIM;     // [m][k]
    const float* Be = Bg + (size_t)e * KDIM * NTOT;   // [k][n]

    float acc[4][4][4] = {};

    // cp.async chunk coordinates
    const int ar = tid >> 3, ac = (tid & 7) * 4;     // A: rows 0..31(+32p), 8 chunks/row
    const int br = tid >> 5, bc = (tid & 31) * 4;    // B: rows 0..7(+8p), 32 chunks/row

    // ldmatrix A: row = wm*64 + mt*16 + (lane&15), chunk = 2*ks + (lane>>4)
    const int a_row = wm * 64 + (lane & 15);
    const int a_chk = lane >> 4;

    auto load_stage = [&](int s, int k0) {
        uint32_t abase = sb + (uint32_t)(s * STGF) * 4u;
        uint32_t bbase = abase + (uint32_t)A_FLOATS * 4u;
#pragma unroll
        for (int p = 0; p < 4; p++) {
            int r = ar + p * 32;
            cpa16(abase + (uint32_t)(r * ASTR + ac) * 4u,
                  Ae + (size_t)(m0 + r) * KDIM + k0 + ac);
        }
#pragma unroll
        for (int p = 0; p < 4; p++) {
            int r = br + p * 8;
            cpa16(bbase + (uint32_t)(r * BSTR + bc) * 4u,
                  Be + (size_t)(k0 + r) * NTOT + n0 + bc);
        }
    };

    // prologue: stages 0 and 1
    load_stage(0, 0);      CP_COMMIT();
    load_stage(1, KC);     CP_COMMIT();

    for (int i = 0; i < NIT; i++) {
        CP_WAIT1();              // stage i resident
        __syncthreads();
        if (i + 2 < NIT) { load_stage((i + 2) % NSTG, (i + 2) * KC); }
        CP_COMMIT();

        const uint32_t As_addr = sb + (uint32_t)((i % NSTG) * STGF) * 4u;
        const float* Bs = sm + (i % NSTG) * STGF + A_FLOATS;

#pragma unroll
        for (int ks = 0; ks < 4; ks++) {
            const int k = ks * 8;
            uint32_t af[4][4], bf[4][2];
#pragma unroll
            for (int mt = 0; mt < 4; mt++) {
                uint32_t addr = As_addr +
                    (uint32_t)((a_row + mt * 16) * ASTR + (2 * ks + a_chk) * 4) * 4u;
                ldsm_x4(af[mt][0], af[mt][1], af[mt][2], af[mt][3], addr);
            }
#pragma unroll
            for (int nt = 0; nt < 4; nt++) {
                int c = wn * 32 + nt * 8 + g;
                bf[nt][0] = cvt_tf32(__float_as_uint(Bs[(k + l4) * BSTR + c]));
                bf[nt][1] = cvt_tf32(__float_as_uint(Bs[(k + l4 + 4) * BSTR + c]));
            }
#pragma unroll
            for (int mt = 0; mt < 4; mt++)
#pragma unroll
                for (int nt = 0; nt < 4; nt++)
                    mma8(acc[mt][nt], af[mt], bf[nt]);
        }
    }

    // ============================ epilogue ============================
#pragma unroll
    for (int mt = 0; mt < 4; mt++) {
#pragma unroll
        for (int nt = 0; nt < 4; nt++) {
            int mrow = m0 + wm * 64 + mt * 16 + g;
            int ncol = n0 + wn * 32 + nt * 8 + 2 * l4;
            float2 bv = *(const float2*)&bias[(size_t)e * NTOT + ncol];
            if (MODE == 0) {
                // (even, odd) col pair = (gate, up); store tf32-rounded act
                float a0 = swiglu(acc[mt][nt][0] + bv.x, acc[mt][nt][1] + bv.y);
                float a1 = swiglu(acc[mt][nt][2] + bv.x, acc[mt][nt][3] + bv.y);
                int io = ncol >> 1;
                g_act[((size_t)e * M_ + mrow)     * IN_ + io] = rtf32(a0);
                g_act[((size_t)e * M_ + mrow + 8) * IN_ + io] = rtf32(a1);
            } else {
                float2 v0 = make_float2(acc[mt][nt][0] + bv.x, acc[mt][nt][1] + bv.y);
                float2 v1 = make_float2(acc[mt][nt][2] + bv.x, acc[mt][nt][3] + bv.y);
                *(float2*)&outp[((size_t)e * M_ + mrow)     * H_ + ncol] = v0;
                *(float2*)&outp[((size_t)e * M_ + mrow + 8) * H_ + ncol] = v1;
            }
        }
    }
}

// ============================ launch ============================
extern "C" void kernel_launch(void* const* d_in, const int* in_sizes, int n_in,
                              void* d_out, int out_size) {
    const float* x  = (const float*)d_in[0];
    const float* w1 = (const float*)d_in[1];
    const float* b1 = (const float*)d_in[2];
    const float* w2 = (const float*)d_in[3];
    const float* b2 = (const float*)d_in[4];
    float* out = (float*)d_out;

    cudaFuncSetAttribute(gemm_mma<0>, cudaFuncAttributeMaxDynamicSharedMemorySize, SMEM_TOTAL);
    cudaFuncSetAttribute(gemm_mma<1>, cudaFuncAttributeMaxDynamicSharedMemorySize, SMEM_TOTAL);

    float *actp, *xrp;
    cudaGetSymbolAddress((void**)&actp, g_act);
    cudaGetSymbolAddress((void**)&xrp,  g_xr);

    // prep: round x only (weights rounded in-register inside the GEMMs)
    round_x<<<1024, 256>>>(x);

    // GEMM1 + bias + SwiGLU -> g_act   (B = w1 native [k][n])
    gemm_mma<0><<<dim3(I2_ / TN, M_ / TM, E_), 256, SMEM_TOTAL>>>(xrp, w1, b1, nullptr);
    // GEMM2 + bias -> out              (B = w2 native [k][n])
    gemm_mma<1><<<dim3(H_ / TN, M_ / TM, E_), 256, SMEM_TOTAL>>>(actp, w2, b2, out);
}

// round 15
// speedup vs baseline: 1.4549x; 1.0154x over previous
#include <cuda_runtime.h>
#include <cstdint>

// ============================ problem constants ============================
static constexpr int E_  = 8;
static constexpr int M_  = 1024;
static constexpr int H_  = 2048;   // K of GEMM1, N of GEMM2
static constexpr int I2_ = 4096;   // w1 out cols (gate/up interleaved)
static constexpr int IN_ = 2048;   // intermediate = I2/2 = K of GEMM2
static constexpr int KDIM = 2048;  // K of both GEMMs

static constexpr int TM = 128, TN = 128, KC = 32;
static constexpr int NSTG = 3;
static constexpr int NIT = KDIM / KC;          // 64

// Both tiles [128 rows][32 k-floats], row stride 36 floats.
// ldmatrix conflict-freedom: 16B-chunk index = (9*row + chunk) mod 8,
// distinct for any 8 consecutive rows at fixed chunk.
static constexpr int TSTR = 36;
static constexpr int T_FLOATS = 128 * TSTR;              // 4608
static constexpr int STGF = 2 * T_FLOATS;                // 9216 floats (A + B)
static constexpr int SMEM_TOTAL = NSTG * STGF * 4;       // 110592 B (2 CTAs/SM)

// ============================ device scratch ============================
__device__ float g_xr [E_ * M_  * KDIM];   // tf32-rounded X       [e][m][k]
__device__ float g_w1t[E_ * I2_ * KDIM];   // tf32 w1 transposed   [e][n][k]
__device__ float g_w2t[E_ * H_  * IN_ ];   // tf32 w2 transposed   [e][n][k]
__device__ float g_act[E_ * M_  * IN_ ];   // tf32 activation      [e][m][i]

// ============================ helpers ============================
__device__ __forceinline__ uint32_t smem_u32(const void* p) {
    uint32_t a;
    asm("{ .reg .u64 t; cvta.to.shared.u64 t, %1; cvt.u32.u64 %0, t; }" : "=r"(a) : "l"(p));
    return a;
}

// fp32 -> tf32 round-to-nearest (HW)
__device__ __forceinline__ float rtf32(float x) {
    uint32_t y;
    asm("cvt.rna.tf32.f32 %0, %1;" : "=r"(y) : "r"(__float_as_uint(x)));
    return __uint_as_float(y);
}

__device__ __forceinline__ void cpa16(uint32_t s, const float* g) {
    asm volatile("cp.async.cg.shared.global [%0], [%1], 16;" :: "r"(s), "l"(g));
}
#define CP_COMMIT() asm volatile("cp.async.commit_group;" ::: "memory")
#define CP_WAIT1()  asm volatile("cp.async.wait_group 1;" ::: "memory")

__device__ __forceinline__ void ldsm_x4(uint32_t& r0, uint32_t& r1,
                                        uint32_t& r2, uint32_t& r3, uint32_t addr) {
    asm volatile("ldmatrix.sync.aligned.m8n8.x4.shared.b16 {%0,%1,%2,%3}, [%4];"
                 : "=r"(r0), "=r"(r1), "=r"(r2), "=r"(r3) : "r"(addr));
}

// m16n8k8 tf32 MMA, D += A*B
__device__ __forceinline__ void mma8(float* d, const uint32_t* a, const uint32_t* b) {
    asm volatile(
        "mma.sync.aligned.m16n8k8.row.col.f32.tf32.tf32.f32 "
        "{%0,%1,%2,%3},{%4,%5,%6,%7},{%8,%9},{%0,%1,%2,%3};"
        : "+f"(d[0]), "+f"(d[1]), "+f"(d[2]), "+f"(d[3])
        : "r"(a[0]), "r"(a[1]), "r"(a[2]), "r"(a[3]), "r"(b[0]), "r"(b[1]));
}

__device__ __forceinline__ float swiglu(float gate, float up) {
    gate = fminf(gate, 7.0f);
    up   = fminf(fmaxf(up, -7.0f), 7.0f);
    float glu = gate * (1.0f / (1.0f + __expf(-1.702f * gate)));
    return (up + 1.0f) * glu;
}

// ============================ prep kernels ============================
__global__ __launch_bounds__(256) void round_x(const float* __restrict__ src) {
    size_t n4 = (size_t)E_ * M_ * KDIM / 4;
    const float4* s4 = (const float4*)src;
    float4* d4 = (float4*)g_xr;
    for (size_t i = (size_t)blockIdx.x * blockDim.x + threadIdx.x; i < n4;
         i += (size_t)gridDim.x * blockDim.x) {
        float4 v = s4[i];
        v.x = rtf32(v.x); v.y = rtf32(v.y); v.z = rtf32(v.z); v.w = rtf32(v.w);
        d4[i] = v;
    }
}

// dst[e][c][r] = rtf32(src[e][r][c]) for one expert slab [R][C].
// Tile: 32 rows x 64 cols, 256 threads, vectorized (float4) global writes.
// Read STS:  t[row][col], bank=(row+col)%32, warp has fixed row + 32 distinct cols. CF.
// Write LDS: t[4k+j][colout], bank=(4k+j+colout)%32; lanes k=lane%8, colout=base+lane/8
//            -> (4a + b + c) covers 0..31 distinct. CF. Each 8-lane group stores
//            8 x float4 = 128B contiguous along output R.
__global__ __launch_bounds__(256) void transpose_rt(const float* __restrict__ src,
                                                    int sel, int R, int C) {
    __shared__ float t[32][65];
    const int e = blockIdx.z;
    const float* s = src + (size_t)e * R * C;
    float* d = (sel == 0 ? g_w1t : g_w2t) + (size_t)e * R * C;
    const int c0 = blockIdx.x * 64, r0 = blockIdx.y * 32;
    const int tid = threadIdx.x;

    // read: 32 rows x 64 cols, scalar coalesced
    {
        const int rr = tid >> 6;          // 0..3
        const int cc = tid & 63;          // 0..63
#pragma unroll
        for (int p = 0; p < 8; p++) {
            int row = rr + p * 4;
            t[row][cc] = rtf32(s[(size_t)(r0 + row) * C + c0 + cc]);
        }
    }
    __syncthreads();

    // write: 64 out-rows x 32 out-cols as float4 along R
    {
        const int k = tid & 7;            // 0..7 -> out-col group 4k..4k+3
        const int cbase = tid >> 3;       // 0..31
#pragma unroll
        for (int p = 0; p < 2; p++) {
            int colout = p * 32 + cbase;  // 0..63
            float4 w;
            w.x = t[4 * k + 0][colout];
            w.y = t[4 * k + 1][colout];
            w.z = t[4 * k + 2][colout];
            w.w = t[4 * k + 3][colout];
            *(float4*)&d[(size_t)(c0 + colout) * R + r0 + 4 * k] = w;
        }
    }
}

// ============================ GEMM ============================
// MODE 0: act = swiglu(X @ w1 + b1) -> g_act   (N total = 4096; B = g_w1t [n][k])
// MODE 1: out = act @ w2 + b2                   (N total = 2048; B = g_w2t [n][k])
template <int MODE>
__global__ __launch_bounds__(256, 2) void gemm_mma(const float* __restrict__ Ag,
                                                   const float* __restrict__ Bg,
                                                   const float* __restrict__ bias,
                                                   float* __restrict__ outp) {
    constexpr int NTOT = (MODE == 0) ? I2_ : H_;
    extern __shared__ __align__(16) float sm[];
    const uint32_t sb = smem_u32(sm);

    const int tid = threadIdx.x;
    const int wid = tid >> 5, lane = tid & 31;
    const int wm = wid >> 2, wn = wid & 3;     // 2 x 4 warp grid, 64x32 tiles
    const int g = lane >> 2, l4 = lane & 3;
    const int e = blockIdx.z;
    const int m0 = blockIdx.y * TM, n0 = blockIdx.x * TN;

    const float* Ae = Ag + (size_t)e * M_ * KDIM;
    const float* Be = Bg + (size_t)e * NTOT * KDIM;   // [n][k]

    float acc[4][4][4] = {};

    // cp.async chunk coordinates (identical pattern for A and B tiles)
    const int cr = tid >> 3, cc = (tid & 7) * 4;     // rows 0..31(+32p), 8 chunks/row

    // ldmatrix A: row = wm*64 + mt*16 + (lane&15), chunk = 2*ks + (lane>>4)
    const int a_row = wm * 64 + (lane & 15);
    const int a_chk = lane >> 4;
    // ldmatrix B: row = wn*32 + p*16 + ((lane>>4)*8) + (lane&7), chunk = 2*ks + ((lane>>3)&1)
    const int b_row = wn * 32 + ((lane >> 4) * 8) + (lane & 7);
    const int b_chk = (lane >> 3) & 1;

    auto load_stage = [&](int s, int k0) {
        uint32_t abase = sb + (uint32_t)(s * STGF) * 4u;
        uint32_t bbase = abase + (uint32_t)T_FLOATS * 4u;
#pragma unroll
        for (int p = 0; p < 4; p++) {
            int r = cr + p * 32;
            cpa16(abase + (uint32_t)(r * TSTR + cc) * 4u,
                  Ae + (size_t)(m0 + r) * KDIM + k0 + cc);
        }
#pragma unroll
        for (int p = 0; p < 4; p++) {
            int r = cr + p * 32;
            cpa16(bbase + (uint32_t)(r * TSTR + cc) * 4u,
                  Be + (size_t)(n0 + r) * KDIM + k0 + cc);
        }
    };

    // prologue: stages 0 and 1
    load_stage(0, 0);      CP_COMMIT();
    load_stage(1, KC);     CP_COMMIT();

    for (int i = 0; i < NIT; i++) {
        CP_WAIT1();              // stage i resident
        __syncthreads();
        if (i + 2 < NIT) { load_stage((i + 2) % NSTG, (i + 2) * KC); }
        CP_COMMIT();

        const uint32_t As_addr = sb + (uint32_t)((i % NSTG) * STGF) * 4u;
        const uint32_t Bs_addr = As_addr + (uint32_t)T_FLOATS * 4u;

#pragma unroll
        for (int ks = 0; ks < 4; ks++) {
            uint32_t af[4][4], bf[4][2];
#pragma unroll
            for (int mt = 0; mt < 4; mt++) {
                uint32_t addr = As_addr +
                    (uint32_t)((a_row + mt * 16) * TSTR + (2 * ks + a_chk) * 4) * 4u;
                ldsm_x4(af[mt][0], af[mt][1], af[mt][2], af[mt][3], addr);
            }
#pragma unroll
            for (int p = 0; p < 2; p++) {   // nt pairs (2p, 2p+1)
                uint32_t addr = Bs_addr +
                    (uint32_t)((b_row + p * 16) * TSTR + (2 * ks + b_chk) * 4) * 4u;
                ldsm_x4(bf[2 * p][0], bf[2 * p][1], bf[2 * p + 1][0], bf[2 * p + 1][1], addr);
            }
#pragma unroll
            for (int mt = 0; mt < 4; mt++)
#pragma unroll
                for (int nt = 0; nt < 4; nt++)
                    mma8(acc[mt][nt], af[mt], bf[nt]);
        }
    }

    // ============================ epilogue ============================
#pragma unroll
    for (int mt = 0; mt < 4; mt++) {
#pragma unroll
        for (int nt = 0; nt < 4; nt++) {
            int mrow = m0 + wm * 64 + mt * 16 + g;
            int ncol = n0 + wn * 32 + nt * 8 + 2 * l4;
            float2 bv = *(const float2*)&bias[(size_t)e * NTOT + ncol];
            if (MODE == 0) {
                // (even, odd) col pair = (gate, up); store tf32-rounded act
                float a0 = swiglu(acc[mt][nt][0] + bv.x, acc[mt][nt][1] + bv.y);
                float a1 = swiglu(acc[mt][nt][2] + bv.x, acc[mt][nt][3] + bv.y);
                int io = ncol >> 1;
                g_act[((size_t)e * M_ + mrow)     * IN_ + io] = rtf32(a0);
                g_act[((size_t)e * M_ + mrow + 8) * IN_ + io] = rtf32(a1);
            } else {
                float2 v0 = make_float2(acc[mt][nt][0] + bv.x, acc[mt][nt][1] + bv.y);
                float2 v1 = make_float2(acc[mt][nt][2] + bv.x, acc[mt][nt][3] + bv.y);
                *(float2*)&outp[((size_t)e * M_ + mrow)     * H_ + ncol] = v0;
                *(float2*)&outp[((size_t)e * M_ + mrow + 8) * H_ + ncol] = v1;
            }
        }
    }
}

// ============================ launch ============================
extern "C" void kernel_launch(void* const* d_in, const int* in_sizes, int n_in,
                              void* d_out, int out_size) {
    const float* x  = (const float*)d_in[0];
    const float* w1 = (const float*)d_in[1];
    const float* b1 = (const float*)d_in[2];
    const float* w2 = (const float*)d_in[3];
    const float* b2 = (const float*)d_in[4];
    float* out = (float*)d_out;

    cudaFuncSetAttribute(gemm_mma<0>, cudaFuncAttributeMaxDynamicSharedMemorySize, SMEM_TOTAL);
    cudaFuncSetAttribute(gemm_mma<1>, cudaFuncAttributeMaxDynamicSharedMemorySize, SMEM_TOTAL);

    float *actp, *w1tp, *w2tp, *xrp;
    cudaGetSymbolAddress((void**)&actp, g_act);
    cudaGetSymbolAddress((void**)&w1tp, g_w1t);
    cudaGetSymbolAddress((void**)&w2tp, g_w2t);
    cudaGetSymbolAddress((void**)&xrp,  g_xr);

    // prep: round x; transpose+round w1 -> [n][k], w2 -> [n][k]
    round_x<<<1024, 256>>>(x);
    transpose_rt<<<dim3(I2_ / 64, H_ / 32, E_), 256>>>(w1, 0, H_, I2_);
    transpose_rt<<<dim3(H_ / 64, IN_ / 32, E_), 256>>>(w2, 1, IN_, H_);

    // GEMM1 + bias + SwiGLU -> g_act
    gemm_mma<0><<<dim3(I2_ / TN, M_ / TM, E_), 256, SMEM_TOTAL>>>(xrp, w1tp, b1, nullptr);
    // GEMM2 + bias -> out
    gemm_mma<1><<<dim3(H_ / TN, M_ / TM, E_), 256, SMEM_TOTAL>>>(actp, w2tp, b2, out);
}